// round 8
// baseline (speedup 1.0000x reference)
#include <cuda_runtime.h>
#include <cuda_bf16.h>
#include <cstdint>

#define NP 50000
#define NA 30000
#define NS 60
#define D  128

// relation order: 0 wb(P->A), 1 w(A->P), 2 c(P->P), 3 cd(P->P), 4 ia(P->S), 5 h(S->P)
#define E_TOT    1500000
#define NDST_TOT 230060
#define NOFF_TOT 230066

// deg bases:  wb 0, w 30000, c 80000, cd 130000, ia 180000, h 180060
// off bases:  wb 0, w 30001, c 80002, cd 130003, ia 180004, h 180065
// srt bases:  wb 0, w 200000, c 400000, cd 900000, ia 1400000, h 1450000
// Wh  bases (floats): w 0, c NA*D, cd (NA+NP)*D, h (NA+2*NP)*D
// agg bases (floats): wb 0, ia NA*D

__device__ int   g_deg[NDST_TOT];
__device__ int   g_off[NOFF_TOT];
__device__ int   g_cur[NDST_TOT];
__device__ int   g_srt[E_TOT];
__device__ float g_Wh[(NA + NP + NP + NS) * D];
__device__ float g_agg[(NA + NS) * D];
// Weights pre-split (hi/lo bf16), transposed to [n][k] row-major.
__device__ __nv_bfloat16 g_Wsw[6][2][16384];

// ===========================================================================
// helpers
// ===========================================================================
__device__ __forceinline__ uint32_t s2u(const void* p) {
    uint32_t a;
    asm("{ .reg .u64 t; cvta.to.shared.u64 t, %1; cvt.u32.u64 %0, t; }"
        : "=r"(a) : "l"(p));
    return a;
}
__device__ __forceinline__ void sts64(uint32_t addr, uint32_t v0, uint32_t v1) {
    asm volatile("st.shared.v2.b32 [%0], {%1, %2};" :: "r"(addr), "r"(v0), "r"(v1));
}
__device__ __forceinline__ void sts128i(uint32_t addr, int4 v) {
    asm volatile("st.shared.v4.b32 [%0], {%1, %2, %3, %4};"
                 :: "r"(addr), "r"(v.x), "r"(v.y), "r"(v.z), "r"(v.w));
}
__device__ __forceinline__ void ldsm_x4(uint32_t* r, uint32_t addr) {
    asm volatile("ldmatrix.sync.aligned.m8n8.x4.shared.b16 {%0,%1,%2,%3}, [%4];"
                 : "=r"(r[0]), "=r"(r[1]), "=r"(r[2]), "=r"(r[3]) : "r"(addr));
}
__device__ __forceinline__ void mma_bf16(float* d, const uint32_t* a,
                                         uint32_t b0, uint32_t b1) {
    asm volatile(
        "mma.sync.aligned.m16n8k16.row.col.f32.bf16.bf16.f32 "
        "{%0,%1,%2,%3}, {%4,%5,%6,%7}, {%8,%9}, {%0,%1,%2,%3};"
        : "+f"(d[0]), "+f"(d[1]), "+f"(d[2]), "+f"(d[3])
        : "r"(a[0]), "r"(a[1]), "r"(a[2]), "r"(a[3]), "r"(b0), "r"(b1));
}

// smem matrix: 128 rows x 136 bf16 (272B pitch)
#define PITCH 272
#define MAT   34816
#define MMA_SMEM_DUAL   (6 * MAT)
#define MMA_SMEM_SINGLE (4 * MAT)

// ===========================================================================
// Fused prep: blocks 0-5 split/transpose weights; blocks 6+ zero g_deg.
// ===========================================================================
__global__ void prep(const float* __restrict__ w0, const float* __restrict__ w1,
                     const float* __restrict__ w2, const float* __restrict__ w3,
                     const float* __restrict__ w4, const float* __restrict__ w5) {
    int b = blockIdx.x;
    if (b < 6) {
        const float* tbl[6] = {w0, w1, w2, w3, w4, w5};
        const float* W = tbl[b];
        __nv_bfloat16* dh = g_Wsw[b][0];
        __nv_bfloat16* dl = g_Wsw[b][1];
        for (int i = threadIdx.x; i < 16384; i += 256) {
            int n = i >> 7, k = i & 127;
            float v = __ldg(&W[k * 128 + n]);
            __nv_bfloat16 hi = __float2bfloat16(v);
            __nv_bfloat16 lo = __float2bfloat16(v - __bfloat162float(hi));
            dh[i] = hi;
            dl[i] = lo;
        }
    } else {
        int i = (b - 6) * 256 + threadIdx.x;
        if (i < NDST_TOT) g_deg[i] = 0;
    }
}

// ===========================================================================
// CSR build
// ===========================================================================
__global__ void count_kernel(const int* __restrict__ d0, const int* __restrict__ d1,
                             const int* __restrict__ d2, const int* __restrict__ d3,
                             const int* __restrict__ d4, const int* __restrict__ d5) {
    int g = blockIdx.x * blockDim.x + threadIdx.x;
    if (g >= 375000) return;
    const int4* dp; int e, db;
    if      (g <  50000) { dp = (const int4*)d0; e = g;          db = 0;      }
    else if (g < 100000) { dp = (const int4*)d1; e = g -  50000; db = 30000;  }
    else if (g < 225000) { dp = (const int4*)d2; e = g - 100000; db = 80000;  }
    else if (g < 350000) { dp = (const int4*)d3; e = g - 225000; db = 130000; }
    else if (g < 362500) { dp = (const int4*)d4; e = g - 350000; db = 180000; }
    else                 { dp = (const int4*)d5; e = g - 362500; db = 180060; }
    int4 v = dp[e];
    atomicAdd(&g_deg[db + v.x], 1);
    atomicAdd(&g_deg[db + v.y], 1);
    atomicAdd(&g_deg[db + v.z], 1);
    atomicAdd(&g_deg[db + v.w], 1);
}

__global__ void scan_kernel() {
    int r = blockIdx.x;
    int n, db, ob;
    switch (r) {
        case 0: n = 30000; db = 0;      ob = 0;      break;
        case 1: n = 50000; db = 30000;  ob = 30001;  break;
        case 2: n = 50000; db = 80000;  ob = 80002;  break;
        case 3: n = 50000; db = 130000; ob = 130003; break;
        case 4: n = 60;    db = 180000; ob = 180004; break;
        default:n = 50000; db = 180060; ob = 180065; break;
    }
    __shared__ int warpsum[32];
    int tid = threadIdx.x;
    int base = 0;
    for (int start = 0; start < n; start += 1024) {
        __syncthreads();
        int i = start + tid;
        int v = (i < n) ? g_deg[db + i] : 0;
        int x = v;
        #pragma unroll
        for (int o = 1; o < 32; o <<= 1) {
            int t = __shfl_up_sync(0xffffffffu, x, o);
            if ((tid & 31) >= o) x += t;
        }
        if ((tid & 31) == 31) warpsum[tid >> 5] = x;
        __syncthreads();
        if (tid < 32) {
            int y = warpsum[tid];
            #pragma unroll
            for (int o = 1; o < 32; o <<= 1) {
                int t = __shfl_up_sync(0xffffffffu, y, o);
                if (tid >= o) y += t;
            }
            warpsum[tid] = y;
        }
        __syncthreads();
        int wb = (tid >= 32) ? warpsum[(tid >> 5) - 1] : 0;
        int excl = base + wb + x - v;
        if (i < n) { g_off[ob + i] = excl; g_cur[db + i] = excl; }
        base += warpsum[31];
    }
    if (tid == 0) g_off[ob + n] = base;
}

__global__ void fill_kernel(const int* __restrict__ s0, const int* __restrict__ d0,
                            const int* __restrict__ s1, const int* __restrict__ d1,
                            const int* __restrict__ s2, const int* __restrict__ d2,
                            const int* __restrict__ s3, const int* __restrict__ d3,
                            const int* __restrict__ s4, const int* __restrict__ d4,
                            const int* __restrict__ s5, const int* __restrict__ d5) {
    int g = blockIdx.x * blockDim.x + threadIdx.x;
    if (g >= 375000) return;
    const int4 *sp, *dp; int e, db, sb;
    if      (g <  50000) { sp = (const int4*)s0; dp = (const int4*)d0; e = g;          db = 0;      sb = 0;       }
    else if (g < 100000) { sp = (const int4*)s1; dp = (const int4*)d1; e = g -  50000; db = 30000;  sb = 200000;  }
    else if (g < 225000) { sp = (const int4*)s2; dp = (const int4*)d2; e = g - 100000; db = 80000;  sb = 400000;  }
    else if (g < 350000) { sp = (const int4*)s3; dp = (const int4*)d3; e = g - 225000; db = 130000; sb = 900000;  }
    else if (g < 362500) { sp = (const int4*)s4; dp = (const int4*)d4; e = g - 350000; db = 180000; sb = 1400000; }
    else                 { sp = (const int4*)s5; dp = (const int4*)d5; e = g - 362500; db = 180060; sb = 1450000; }
    int4 dv = dp[e];
    int4 sv = sp[e];
    int p0 = atomicAdd(&g_cur[db + dv.x], 1);
    int p1 = atomicAdd(&g_cur[db + dv.y], 1);
    int p2 = atomicAdd(&g_cur[db + dv.z], 1);
    int p3 = atomicAdd(&g_cur[db + dv.w], 1);
    g_srt[sb + p0] = sv.x;
    g_srt[sb + p1] = sv.y;
    g_srt[sb + p2] = sv.z;
    g_srt[sb + p3] = sv.w;
}

// ===========================================================================
// Tensor-core GEMM tile (verified round-7 body, now a device function).
// 256 threads, 128(M)x128(N) tile; warp w owns rows w*16..w*16+15.
// ===========================================================================
template <int NW>
__device__ __forceinline__ void gemm_tile(
    uint32_t sb,
    const float* __restrict__ A, int M, int m0,
    int w0, const float* __restrict__ bias0, float* __restrict__ C0, int mask0,
    int w1, const float* __restrict__ bias1, float* __restrict__ C1) {
    int tid = threadIdx.x;
    int warp = tid >> 5, lane = tid & 31;

    // ---- Stage A: fp32 -> hi/lo bf16, pitch-272 smem ----
    for (int i = tid; i < 4096; i += 256) {      // float4 units
        int row = i >> 5, qf = i & 31;           // col = qf*4
        float4 v = make_float4(0.f, 0.f, 0.f, 0.f);
        if (m0 + row < M) v = *(const float4*)&A[(size_t)(m0 + row) * 128 + qf * 4];
        __nv_bfloat162 h01, h23, l01, l23;
        h01.x = __float2bfloat16(v.x); h01.y = __float2bfloat16(v.y);
        h23.x = __float2bfloat16(v.z); h23.y = __float2bfloat16(v.w);
        l01.x = __float2bfloat16(v.x - __bfloat162float(h01.x));
        l01.y = __float2bfloat16(v.y - __bfloat162float(h01.y));
        l23.x = __float2bfloat16(v.z - __bfloat162float(h23.x));
        l23.y = __float2bfloat16(v.w - __bfloat162float(h23.y));
        uint32_t addr = sb + (uint32_t)row * PITCH + (uint32_t)qf * 8;
        sts64(addr,       *(uint32_t*)&h01, *(uint32_t*)&h23);
        sts64(addr + MAT, *(uint32_t*)&l01, *(uint32_t*)&l23);
    }

    // ---- Stage B: copy pre-split transposed weights, pitch 272 ----
    #pragma unroll
    for (int o = 0; o < NW; o++) {
        int w = o ? w1 : w0;
        const int4* srcH = (const int4*)g_Wsw[w][0];
        const int4* srcL = (const int4*)g_Wsw[w][1];
        uint32_t bb = sb + (uint32_t)(2 + 2 * o) * MAT;
        for (int i = tid; i < 2048; i += 256) {  // int4 units (16B = 8 bf16)
            int row = i >> 4, q = i & 15;
            uint32_t addr = bb + (uint32_t)row * PITCH + (uint32_t)q * 16;
            sts128i(addr,       srcH[i]);
            sts128i(addr + MAT, srcL[i]);
        }
    }
    __syncthreads();

    // ---- Main loop ----
    int quad = lane >> 3, r = lane & 7;
    uint32_t aoff = sb + (uint32_t)((warp * 16 + r + (quad & 1) * 8) * PITCH
                                    + (quad >> 1) * 16);
    uint32_t boffc = (uint32_t)((r + (quad >> 1) * 8) * PITCH + (quad & 1) * 16);

    float acc[NW][16][4];
    #pragma unroll
    for (int o = 0; o < NW; o++)
        #pragma unroll
        for (int t = 0; t < 16; t++)
            #pragma unroll
            for (int j = 0; j < 4; j++) acc[o][t][j] = 0.f;

    for (int ks = 0; ks < 8; ks++) {
        uint32_t kb = (uint32_t)ks * 32;         // k0*2 bytes
        uint32_t ah[4], al[4];
        ldsm_x4(ah, aoff + kb);
        ldsm_x4(al, aoff + MAT + kb);
        #pragma unroll
        for (int o = 0; o < NW; o++) {
            uint32_t bbase = sb + (uint32_t)(2 + 2 * o) * MAT + boffc + kb;
            uint32_t bf[32];
            #pragma unroll
            for (int i = 0; i < 8; i++)
                ldsm_x4(&bf[4 * i], bbase + (uint32_t)i * (16 * PITCH));
            #pragma unroll
            for (int t = 0; t < 16; t++) {
                mma_bf16(acc[o][t], ah, bf[2 * t], bf[2 * t + 1]);
                mma_bf16(acc[o][t], al, bf[2 * t], bf[2 * t + 1]);
            }
            #pragma unroll
            for (int i = 0; i < 8; i++)
                ldsm_x4(&bf[4 * i], bbase + MAT + (uint32_t)i * (16 * PITCH));
            #pragma unroll
            for (int t = 0; t < 16; t++)
                mma_bf16(acc[o][t], ah, bf[2 * t], bf[2 * t + 1]);
        }
    }

    // ---- Epilogue ----
    int g = lane >> 2, cq = (lane & 3) * 2;
    int r0 = m0 + warp * 16 + g;
    int r1 = r0 + 8;
    bool ok0 = r0 < M, ok1 = r1 < M;
    #pragma unroll
    for (int o = 0; o < NW; o++) {
        const float* bias = o ? bias1 : bias0;
        float* C = o ? C1 : C0;
        bool z0 = false, z1 = false;
        if (o == 0 && mask0 >= 0) {
            if (ok0) z0 = (g_off[mask0 + r0 + 1] - g_off[mask0 + r0]) == 0;
            if (ok1) z1 = (g_off[mask0 + r1 + 1] - g_off[mask0 + r1]) == 0;
        }
        #pragma unroll
        for (int t = 0; t < 16; t++) {
            float2 bv = *(const float2*)&bias[t * 8 + cq];
            if (ok0) {
                float2 v;
                if (z0) v = make_float2(0.f, 0.f);
                else    v = make_float2(acc[o][t][0] + bv.x, acc[o][t][1] + bv.y);
                *(float2*)&C[(size_t)r0 * 128 + t * 8 + cq] = v;
            }
            if (ok1) {
                float2 v;
                if (z1) v = make_float2(0.f, 0.f);
                else    v = make_float2(acc[o][t][2] + bv.x, acc[o][t][3] + bv.y);
                *(float2*)&C[(size_t)r1 * 128 + t * 8 + cq] = v;
            }
        }
    }
}

// ---------------------------------------------------------------------------
// All project-first GEMMs in ONE launch:
//   blocks [0,391)  : dual c+cd over x_paper
//   blocks [391,626): w over x_author
//   block  626      : h over x_subject
// ---------------------------------------------------------------------------
#define N_CD 391
#define N_W  235
__global__ void __launch_bounds__(256, 1)
allgemm(const float* __restrict__ xp, const float* __restrict__ xa,
        const float* __restrict__ xs,
        const float* __restrict__ bc, const float* __restrict__ bcd,
        const float* __restrict__ bw, const float* __restrict__ bh) {
    extern __shared__ char smraw[];
    uint32_t sb = s2u(smraw);
    int b = blockIdx.x;
    if (b < N_CD) {
        gemm_tile<2>(sb, xp, NP, b * 128,
                     2, bc,  g_Wh + NA * D, -1,
                     3, bcd, g_Wh + (NA + NP) * D);
    } else if (b < N_CD + N_W) {
        gemm_tile<1>(sb, xa, NA, (b - N_CD) * 128,
                     1, bw, g_Wh, -1, 0, nullptr, nullptr);
    } else {
        gemm_tile<1>(sb, xs, NS, 0,
                     5, bh, g_Wh + (NA + 2 * NP) * D, -1, 0, nullptr, nullptr);
    }
}

// ---------------------------------------------------------------------------
// Epilogue GEMMs in ONE launch: blocks [0,235) wb -> out_author; block 235 ia.
// ---------------------------------------------------------------------------
__global__ void __launch_bounds__(256, 1)
epigemm(const float* __restrict__ bwb, const float* __restrict__ bia,
        float* __restrict__ outA, float* __restrict__ outS) {
    extern __shared__ char smraw[];
    uint32_t sb = s2u(smraw);
    int b = blockIdx.x;
    if (b < N_W) {
        gemm_tile<1>(sb, g_agg, NA, b * 128,
                     0, bwb, outA, 0, 0, nullptr, nullptr);
    } else {
        gemm_tile<1>(sb, g_agg + NA * D, NS, 0,
                     4, bia, outS, 180004, 0, nullptr, nullptr);
    }
}

// ===========================================================================
// Fused raw-feature aggregations: author (blocks<3750) + subject (30 blocks).
// ===========================================================================
__global__ void aggAS(const float* __restrict__ xp) {
    int b = blockIdx.x;
    if (b < 3750) {
        int w = b * 8 + (threadIdx.x >> 5);
        if (w >= NA) return;
        int lane = threadIdx.x & 31;
        int s = g_off[w];
        int e = g_off[w + 1];
        int cnt = e - s;
        float4 sum = make_float4(0.f, 0.f, 0.f, 0.f);
        int idx = s;
        for (; idx + 3 < e; idx += 4) {
            int a0 = g_srt[idx];
            int a1 = g_srt[idx + 1];
            int a2 = g_srt[idx + 2];
            int a3 = g_srt[idx + 3];
            float4 v0 = *(const float4*)&xp[a0 * D + lane * 4];
            float4 v1 = *(const float4*)&xp[a1 * D + lane * 4];
            float4 v2 = *(const float4*)&xp[a2 * D + lane * 4];
            float4 v3 = *(const float4*)&xp[a3 * D + lane * 4];
            sum.x += (v0.x + v1.x) + (v2.x + v3.x);
            sum.y += (v0.y + v1.y) + (v2.y + v3.y);
            sum.z += (v0.z + v1.z) + (v2.z + v3.z);
            sum.w += (v0.w + v1.w) + (v2.w + v3.w);
        }
        for (; idx < e; idx++) {
            int a0 = g_srt[idx];
            float4 v0 = *(const float4*)&xp[a0 * D + lane * 4];
            sum.x += v0.x; sum.y += v0.y; sum.z += v0.z; sum.w += v0.w;
        }
        float inv = (cnt > 0) ? 1.f / (float)cnt : 0.f;
        *(float4*)&g_agg[w * D + lane * 4] =
            make_float4(sum.x * inv, sum.y * inv, sum.z * inv, sum.w * inv);
    } else {
        int dno = (b - 3750) * 2 + (threadIdx.x >> 7);
        int j = threadIdx.x & 127;
        if (dno >= NS) return;
        int s = g_off[180004 + dno];
        int e = g_off[180004 + dno + 1];
        int cnt = e - s;
        float sum = 0.f;
        int idx = s;
        for (; idx + 3 < e; idx += 4) {
            int a = g_srt[1400000 + idx];
            int bb = g_srt[1400000 + idx + 1];
            int c = g_srt[1400000 + idx + 2];
            int d = g_srt[1400000 + idx + 3];
            sum += xp[a * D + j] + xp[bb * D + j] + xp[c * D + j] + xp[d * D + j];
        }
        for (; idx < e; idx++) sum += xp[g_srt[1400000 + idx] * D + j];
        g_agg[(NA + dno) * D + j] = (cnt > 0) ? sum / (float)cnt : 0.f;
    }
}

// ===========================================================================
// h_paper: one warp per paper dst, fused over 4 relations (w, c, cd, h).
// ===========================================================================
__global__ void agg_paper(float* __restrict__ out) {
    int w = (blockIdx.x * blockDim.x + threadIdx.x) >> 5;
    if (w >= NP) return;
    int lane = threadIdx.x & 31;
    float4 acc = make_float4(0.f, 0.f, 0.f, 0.f);

    const int offB[4] = {30001, 80002, 130003, 180065};
    const int srtB[4] = {200000, 400000, 900000, 1450000};
    const int whB[4]  = {0, NA * D, (NA + NP) * D, (NA + 2 * NP) * D};

    #pragma unroll
    for (int rr = 0; rr < 4; rr++) {
        int s = g_off[offB[rr] + w];
        int e = g_off[offB[rr] + w + 1];
        int cnt = e - s;
        if (cnt > 0) {
            const float* whb = g_Wh + whB[rr];
            float4 sum = make_float4(0.f, 0.f, 0.f, 0.f);
            int idx = s;
            for (; idx + 3 < e; idx += 4) {
                int a0 = g_srt[srtB[rr] + idx];
                int a1 = g_srt[srtB[rr] + idx + 1];
                int a2 = g_srt[srtB[rr] + idx + 2];
                int a3 = g_srt[srtB[rr] + idx + 3];
                float4 v0 = *(const float4*)&whb[a0 * D + lane * 4];
                float4 v1 = *(const float4*)&whb[a1 * D + lane * 4];
                float4 v2 = *(const float4*)&whb[a2 * D + lane * 4];
                float4 v3 = *(const float4*)&whb[a3 * D + lane * 4];
                sum.x += (v0.x + v1.x) + (v2.x + v3.x);
                sum.y += (v0.y + v1.y) + (v2.y + v3.y);
                sum.z += (v0.z + v1.z) + (v2.z + v3.z);
                sum.w += (v0.w + v1.w) + (v2.w + v3.w);
            }
            for (; idx < e; idx++) {
                int a0 = g_srt[srtB[rr] + idx];
                float4 v0 = *(const float4*)&whb[a0 * D + lane * 4];
                sum.x += v0.x; sum.y += v0.y; sum.z += v0.z; sum.w += v0.w;
            }
            float inv = 1.f / (float)cnt;
            acc.x += sum.x * inv; acc.y += sum.y * inv;
            acc.z += sum.z * inv; acc.w += sum.w * inv;
        }
    }
    *(float4*)&out[w * D + lane * 4] = acc;
}

// ===========================================================================
extern "C" void kernel_launch(void* const* d_in, const int* in_sizes, int n_in,
                              void* d_out, int out_size) {
    const float* x_paper   = (const float*)d_in[0];
    const float* x_author  = (const float*)d_in[1];
    const float* x_subject = (const float*)d_in[2];
    const float* W_wb = (const float*)d_in[3];  const float* b_wb = (const float*)d_in[4];
    const float* W_w  = (const float*)d_in[5];  const float* b_w  = (const float*)d_in[6];
    const float* W_c  = (const float*)d_in[7];  const float* b_c  = (const float*)d_in[8];
    const float* W_cd = (const float*)d_in[9];  const float* b_cd = (const float*)d_in[10];
    const float* W_ia = (const float*)d_in[11]; const float* b_ia = (const float*)d_in[12];
    const float* W_h  = (const float*)d_in[13]; const float* b_h  = (const float*)d_in[14];
    const int* src_wb = (const int*)d_in[15];   const int* dst_wb = (const int*)d_in[16];
    const int* src_w  = (const int*)d_in[17];   const int* dst_w  = (const int*)d_in[18];
    const int* src_c  = (const int*)d_in[19];   const int* dst_c  = (const int*)d_in[20];
    const int* src_cd = (const int*)d_in[21];   const int* dst_cd = (const int*)d_in[22];
    const int* src_ia = (const int*)d_in[23];   const int* dst_ia = (const int*)d_in[24];
    const int* src_h  = (const int*)d_in[25];   const int* dst_h  = (const int*)d_in[26];

    float* out         = (float*)d_out;
    float* out_paper   = out;
    float* out_author  = out + NP * D;
    float* out_subject = out + (NP + NA) * D;

    static cudaStream_t s1 = nullptr;
    static cudaEvent_t evW, evB, evC, evD;
    if (s1 == nullptr) {
        cudaStreamCreateWithFlags(&s1, cudaStreamNonBlocking);
        cudaEventCreateWithFlags(&evW, cudaEventDisableTiming);
        cudaEventCreateWithFlags(&evB, cudaEventDisableTiming);
        cudaEventCreateWithFlags(&evC, cudaEventDisableTiming);
        cudaEventCreateWithFlags(&evD, cudaEventDisableTiming);
        cudaFuncSetAttribute(allgemm, cudaFuncAttributeMaxDynamicSharedMemorySize,
                             MMA_SMEM_DUAL);
        cudaFuncSetAttribute(epigemm, cudaFuncAttributeMaxDynamicSharedMemorySize,
                             MMA_SMEM_SINGLE);
    }

    // s0: prep (weights split + deg zero) — both chains branch from here.
    prep<<<6 + (NDST_TOT + 255) / 256, 256>>>(W_wb, W_w, W_c, W_cd, W_ia, W_h);
    cudaEventRecord(evW, 0);

    // s1: all project-first GEMMs in one launch.
    cudaStreamWaitEvent(s1, evW, 0);
    allgemm<<<N_CD + N_W + 1, 256, MMA_SMEM_DUAL, s1>>>(
        x_paper, x_author, x_subject, b_c, b_cd, b_w, b_h);
    cudaEventRecord(evB, s1);

    // s0: CSR build + raw-feature aggregations.
    count_kernel<<<(375000 + 255) / 256, 256>>>(dst_wb, dst_w, dst_c, dst_cd,
                                                dst_ia, dst_h);
    scan_kernel<<<6, 1024>>>();
    fill_kernel<<<(375000 + 255) / 256, 256>>>(src_wb, dst_wb, src_w, dst_w,
                                               src_c, dst_c, src_cd, dst_cd,
                                               src_ia, dst_ia, src_h, dst_h);
    aggAS<<<3780, 256>>>(x_paper);
    cudaEventRecord(evC, 0);

    // s1: epilogue GEMMs (need g_agg + g_off + weights).
    cudaStreamWaitEvent(s1, evC, 0);
    epigemm<<<N_W + 1, 256, MMA_SMEM_SINGLE, s1>>>(
        b_wb, b_ia, out_author, out_subject);
    cudaEventRecord(evD, s1);

    // s0: fused 4-relation paper gather (needs g_Wh + CSR).
    cudaStreamWaitEvent(0, evB, 0);
    agg_paper<<<(NP * 32 + 255) / 256, 256>>>(out_paper);

    // join
    cudaStreamWaitEvent(0, evD, 0);
}

// round 9
// speedup vs baseline: 1.1841x; 1.1841x over previous
#include <cuda_runtime.h>
#include <cuda_bf16.h>
#include <cstdint>

#define NP 50000
#define NA 30000
#define NS 60
#define D  128

// relation order: 0 wb(P->A), 1 w(A->P), 2 c(P->P), 3 cd(P->P), 4 ia(P->S), 5 h(S->P)
#define E_TOT    1500000
#define NDST_TOT 230060
#define NDST_PAD 245760   // 15 chunks * 16384
#define NOFF_TOT 230066
#define NCHUNK   15

// deg bases:  wb 0, w 30000, c 80000, cd 130000, ia 180000, h 180060
// off bases:  wb 0, w 30001, c 80002, cd 130003, ia 180004, h 180065
// srt bases:  wb 0, w 200000, c 400000, cd 900000, ia 1400000, h 1450000
// Wh  bases (floats): w 0, c NA*D, cd (NA+NP)*D, h (NA+2*NP)*D
// agg bases (floats): wb 0, ia NA*D

__device__ int   g_deg[NDST_PAD];
__device__ int   g_S[NDST_PAD];
__device__ int   g_chain[NCHUNK];
__device__ int   g_off[NOFF_TOT];
__device__ int   g_cur[NDST_TOT];
__device__ int   g_srt[E_TOT];
__device__ float g_Wh[(NA + NP + NP + NS) * D];
__device__ float g_agg[(NA + NS) * D];
__device__ __nv_bfloat16 g_Wsw[6][2][16384];

// ===========================================================================
// helpers
// ===========================================================================
__device__ __forceinline__ uint32_t s2u(const void* p) {
    uint32_t a;
    asm("{ .reg .u64 t; cvta.to.shared.u64 t, %1; cvt.u32.u64 %0, t; }"
        : "=r"(a) : "l"(p));
    return a;
}
__device__ __forceinline__ void sts64(uint32_t addr, uint32_t v0, uint32_t v1) {
    asm volatile("st.shared.v2.b32 [%0], {%1, %2};" :: "r"(addr), "r"(v0), "r"(v1));
}
__device__ __forceinline__ void sts128i(uint32_t addr, int4 v) {
    asm volatile("st.shared.v4.b32 [%0], {%1, %2, %3, %4};"
                 :: "r"(addr), "r"(v.x), "r"(v.y), "r"(v.z), "r"(v.w));
}
__device__ __forceinline__ void ldsm_x4(uint32_t* r, uint32_t addr) {
    asm volatile("ldmatrix.sync.aligned.m8n8.x4.shared.b16 {%0,%1,%2,%3}, [%4];"
                 : "=r"(r[0]), "=r"(r[1]), "=r"(r[2]), "=r"(r[3]) : "r"(addr));
}
__device__ __forceinline__ void mma_bf16(float* d, const uint32_t* a,
                                         uint32_t b0, uint32_t b1) {
    asm volatile(
        "mma.sync.aligned.m16n8k16.row.col.f32.bf16.bf16.f32 "
        "{%0,%1,%2,%3}, {%4,%5,%6,%7}, {%8,%9}, {%0,%1,%2,%3};"
        : "+f"(d[0]), "+f"(d[1]), "+f"(d[2]), "+f"(d[3])
        : "r"(a[0]), "r"(a[1]), "r"(a[2]), "r"(a[3]), "r"(b0), "r"(b1));
}

#define PITCH 272
#define MAT   34816
#define MMA_SMEM_DUAL   (6 * MAT)
#define MMA_SMEM_SINGLE (4 * MAT)

// ===========================================================================
// prep: blocks 0-5 split/transpose weights; block 6 also inits scan chain;
// blocks 6+ zero the padded degree array.
// ===========================================================================
__global__ void prep(const float* __restrict__ w0, const float* __restrict__ w1,
                     const float* __restrict__ w2, const float* __restrict__ w3,
                     const float* __restrict__ w4, const float* __restrict__ w5) {
    int b = blockIdx.x;
    if (b < 6) {
        const float* tbl[6] = {w0, w1, w2, w3, w4, w5};
        const float* W = tbl[b];
        __nv_bfloat16* dh = g_Wsw[b][0];
        __nv_bfloat16* dl = g_Wsw[b][1];
        for (int i = threadIdx.x; i < 16384; i += 256) {
            int n = i >> 7, k = i & 127;
            float v = __ldg(&W[k * 128 + n]);
            __nv_bfloat16 hi = __float2bfloat16(v);
            __nv_bfloat16 lo = __float2bfloat16(v - __bfloat162float(hi));
            dh[i] = hi;
            dl[i] = lo;
        }
    } else {
        if (b == 6 && threadIdx.x < NCHUNK) g_chain[threadIdx.x] = -1;
        int i = (b - 6) * 256 + threadIdx.x;
        if (i < NDST_PAD) g_deg[i] = 0;
    }
}

// ===========================================================================
// CSR build
// ===========================================================================
__global__ void count_kernel(const int* __restrict__ d0, const int* __restrict__ d1,
                             const int* __restrict__ d2, const int* __restrict__ d3,
                             const int* __restrict__ d4, const int* __restrict__ d5) {
    int g = blockIdx.x * blockDim.x + threadIdx.x;
    if (g >= 375000) return;
    const int4* dp; int e, db;
    if      (g <  50000) { dp = (const int4*)d0; e = g;          db = 0;      }
    else if (g < 100000) { dp = (const int4*)d1; e = g -  50000; db = 30000;  }
    else if (g < 225000) { dp = (const int4*)d2; e = g - 100000; db = 80000;  }
    else if (g < 350000) { dp = (const int4*)d3; e = g - 225000; db = 130000; }
    else if (g < 362500) { dp = (const int4*)d4; e = g - 350000; db = 180000; }
    else                 { dp = (const int4*)d5; e = g - 362500; db = 180060; }
    int4 v = dp[e];
    atomicAdd(&g_deg[db + v.x], 1);
    atomicAdd(&g_deg[db + v.y], 1);
    atomicAdd(&g_deg[db + v.z], 1);
    atomicAdd(&g_deg[db + v.w], 1);
}

// ---------------------------------------------------------------------------
// Global exclusive scan of g_deg[0..NDST_PAD) into g_S, 15 chained blocks.
// 1024 threads x 16 elems. Chain depth 15; all blocks co-resident.
// ---------------------------------------------------------------------------
__global__ void __launch_bounds__(1024, 1) scan_main() {
    __shared__ int warpsum[32];
    __shared__ int s_prev;
    int b = blockIdx.x;
    int tid = threadIdx.x;
    int wid = tid >> 5, lane = tid & 31;
    int base = b * 16384 + tid * 16;

    int v[16];
    {
        const int4* p = (const int4*)g_deg + (base >> 2);
        int4 a0 = p[0], a1 = p[1], a2 = p[2], a3 = p[3];
        v[0]=a0.x; v[1]=a0.y; v[2]=a0.z; v[3]=a0.w;
        v[4]=a1.x; v[5]=a1.y; v[6]=a1.z; v[7]=a1.w;
        v[8]=a2.x; v[9]=a2.y; v[10]=a2.z; v[11]=a2.w;
        v[12]=a3.x; v[13]=a3.y; v[14]=a3.z; v[15]=a3.w;
    }
    int incl[16];
    int s = 0;
    #pragma unroll
    for (int j = 0; j < 16; j++) { s += v[j]; incl[j] = s; }
    int tot = s;

    int winc = tot;
    #pragma unroll
    for (int o = 1; o < 32; o <<= 1) {
        int t = __shfl_up_sync(0xffffffffu, winc, o);
        if (lane >= o) winc += t;
    }
    if (lane == 31) warpsum[wid] = winc;
    __syncthreads();
    if (tid < 32) {
        int y = warpsum[tid];
        #pragma unroll
        for (int o = 1; o < 32; o <<= 1) {
            int t = __shfl_up_sync(0xffffffffu, y, o);
            if (tid >= o) y += t;
        }
        warpsum[tid] = y;
    }
    __syncthreads();
    int blk_excl = ((wid > 0) ? warpsum[wid - 1] : 0) + (winc - tot);
    int blk_total = warpsum[31];

    if (tid == 0) {
        int prev = 0;
        if (b > 0) while ((prev = atomicAdd(&g_chain[b - 1], 0)) < 0) { }
        atomicExch(&g_chain[b], prev + blk_total);
        s_prev = prev;
    }
    __syncthreads();
    int ex0 = s_prev + blk_excl;

    int4* q = (int4*)g_S + (base >> 2);
    int4 o0, o1, o2, o3;
    o0.x=ex0+incl[0]-v[0];  o0.y=ex0+incl[1]-v[1];  o0.z=ex0+incl[2]-v[2];  o0.w=ex0+incl[3]-v[3];
    o1.x=ex0+incl[4]-v[4];  o1.y=ex0+incl[5]-v[5];  o1.z=ex0+incl[6]-v[6];  o1.w=ex0+incl[7]-v[7];
    o2.x=ex0+incl[8]-v[8];  o2.y=ex0+incl[9]-v[9];  o2.z=ex0+incl[10]-v[10]; o2.w=ex0+incl[11]-v[11];
    o3.x=ex0+incl[12]-v[12]; o3.y=ex0+incl[13]-v[13]; o3.z=ex0+incl[14]-v[14]; o3.w=ex0+incl[15]-v[15];
    q[0]=o0; q[1]=o1; q[2]=o2; q[3]=o3;
}

// ---------------------------------------------------------------------------
// remap: per-relation offsets from the global scan (relations contiguous).
// ---------------------------------------------------------------------------
__global__ void remap_kernel() {
    int j = blockIdx.x * blockDim.x + threadIdx.x;
    if (j >= NOFF_TOT) return;
    int i, db, n;
    if      (j <  30001) { i = j;          db = 0;      n = 30000; }
    else if (j <  80002) { i = j -  30001; db = 30000;  n = 50000; }
    else if (j < 130003) { i = j -  80002; db = 80000;  n = 50000; }
    else if (j < 180004) { i = j - 130003; db = 130000; n = 50000; }
    else if (j < 180065) { i = j - 180004; db = 180000; n = 60;    }
    else                 { i = j - 180065; db = 180060; n = 50000; }
    int v = g_S[db + i] - g_S[db];
    g_off[j] = v;
    if (i < n) g_cur[db + i] = v;
}

__global__ void fill_kernel(const int* __restrict__ s0, const int* __restrict__ d0,
                            const int* __restrict__ s1, const int* __restrict__ d1,
                            const int* __restrict__ s2, const int* __restrict__ d2,
                            const int* __restrict__ s3, const int* __restrict__ d3,
                            const int* __restrict__ s4, const int* __restrict__ d4,
                            const int* __restrict__ s5, const int* __restrict__ d5) {
    int g = blockIdx.x * blockDim.x + threadIdx.x;
    if (g >= 375000) return;
    const int4 *sp, *dp; int e, db, sb;
    if      (g <  50000) { sp = (const int4*)s0; dp = (const int4*)d0; e = g;          db = 0;      sb = 0;       }
    else if (g < 100000) { sp = (const int4*)s1; dp = (const int4*)d1; e = g -  50000; db = 30000;  sb = 200000;  }
    else if (g < 225000) { sp = (const int4*)s2; dp = (const int4*)d2; e = g - 100000; db = 80000;  sb = 400000;  }
    else if (g < 350000) { sp = (const int4*)s3; dp = (const int4*)d3; e = g - 225000; db = 130000; sb = 900000;  }
    else if (g < 362500) { sp = (const int4*)s4; dp = (const int4*)d4; e = g - 350000; db = 180000; sb = 1400000; }
    else                 { sp = (const int4*)s5; dp = (const int4*)d5; e = g - 362500; db = 180060; sb = 1450000; }
    int4 dv = dp[e];
    int4 sv = sp[e];
    int p0 = atomicAdd(&g_cur[db + dv.x], 1);
    int p1 = atomicAdd(&g_cur[db + dv.y], 1);
    int p2 = atomicAdd(&g_cur[db + dv.z], 1);
    int p3 = atomicAdd(&g_cur[db + dv.w], 1);
    g_srt[sb + p0] = sv.x;
    g_srt[sb + p1] = sv.y;
    g_srt[sb + p2] = sv.z;
    g_srt[sb + p3] = sv.w;
}

// ===========================================================================
// Tensor-core GEMM tile (verified round-7 body).
// ===========================================================================
template <int NW>
__device__ __forceinline__ void gemm_tile(
    uint32_t sb,
    const float* __restrict__ A, int M, int m0,
    int w0, const float* __restrict__ bias0, float* __restrict__ C0, int mask0,
    int w1, const float* __restrict__ bias1, float* __restrict__ C1) {
    int tid = threadIdx.x;
    int warp = tid >> 5, lane = tid & 31;

    for (int i = tid; i < 4096; i += 256) {
        int row = i >> 5, qf = i & 31;
        float4 v = make_float4(0.f, 0.f, 0.f, 0.f);
        if (m0 + row < M) v = *(const float4*)&A[(size_t)(m0 + row) * 128 + qf * 4];
        __nv_bfloat162 h01, h23, l01, l23;
        h01.x = __float2bfloat16(v.x); h01.y = __float2bfloat16(v.y);
        h23.x = __float2bfloat16(v.z); h23.y = __float2bfloat16(v.w);
        l01.x = __float2bfloat16(v.x - __bfloat162float(h01.x));
        l01.y = __float2bfloat16(v.y - __bfloat162float(h01.y));
        l23.x = __float2bfloat16(v.z - __bfloat162float(h23.x));
        l23.y = __float2bfloat16(v.w - __bfloat162float(h23.y));
        uint32_t addr = sb + (uint32_t)row * PITCH + (uint32_t)qf * 8;
        sts64(addr,       *(uint32_t*)&h01, *(uint32_t*)&h23);
        sts64(addr + MAT, *(uint32_t*)&l01, *(uint32_t*)&l23);
    }

    #pragma unroll
    for (int o = 0; o < NW; o++) {
        int w = o ? w1 : w0;
        const int4* srcH = (const int4*)g_Wsw[w][0];
        const int4* srcL = (const int4*)g_Wsw[w][1];
        uint32_t bb = sb + (uint32_t)(2 + 2 * o) * MAT;
        for (int i = tid; i < 2048; i += 256) {
            int row = i >> 4, q = i & 15;
            uint32_t addr = bb + (uint32_t)row * PITCH + (uint32_t)q * 16;
            sts128i(addr,       srcH[i]);
            sts128i(addr + MAT, srcL[i]);
        }
    }
    __syncthreads();

    int quad = lane >> 3, r = lane & 7;
    uint32_t aoff = sb + (uint32_t)((warp * 16 + r + (quad & 1) * 8) * PITCH
                                    + (quad >> 1) * 16);
    uint32_t boffc = (uint32_t)((r + (quad >> 1) * 8) * PITCH + (quad & 1) * 16);

    float acc[NW][16][4];
    #pragma unroll
    for (int o = 0; o < NW; o++)
        #pragma unroll
        for (int t = 0; t < 16; t++)
            #pragma unroll
            for (int j = 0; j < 4; j++) acc[o][t][j] = 0.f;

    for (int ks = 0; ks < 8; ks++) {
        uint32_t kb = (uint32_t)ks * 32;
        uint32_t ah[4], al[4];
        ldsm_x4(ah, aoff + kb);
        ldsm_x4(al, aoff + MAT + kb);
        #pragma unroll
        for (int o = 0; o < NW; o++) {
            uint32_t bbase = sb + (uint32_t)(2 + 2 * o) * MAT + boffc + kb;
            uint32_t bf[32];
            #pragma unroll
            for (int i = 0; i < 8; i++)
                ldsm_x4(&bf[4 * i], bbase + (uint32_t)i * (16 * PITCH));
            #pragma unroll
            for (int t = 0; t < 16; t++) {
                mma_bf16(acc[o][t], ah, bf[2 * t], bf[2 * t + 1]);
                mma_bf16(acc[o][t], al, bf[2 * t], bf[2 * t + 1]);
            }
            #pragma unroll
            for (int i = 0; i < 8; i++)
                ldsm_x4(&bf[4 * i], bbase + MAT + (uint32_t)i * (16 * PITCH));
            #pragma unroll
            for (int t = 0; t < 16; t++)
                mma_bf16(acc[o][t], ah, bf[2 * t], bf[2 * t + 1]);
        }
    }

    int g = lane >> 2, cq = (lane & 3) * 2;
    int r0 = m0 + warp * 16 + g;
    int r1 = r0 + 8;
    bool ok0 = r0 < M, ok1 = r1 < M;
    #pragma unroll
    for (int o = 0; o < NW; o++) {
        const float* bias = o ? bias1 : bias0;
        float* C = o ? C1 : C0;
        bool z0 = false, z1 = false;
        if (o == 0 && mask0 >= 0) {
            if (ok0) z0 = (g_off[mask0 + r0 + 1] - g_off[mask0 + r0]) == 0;
            if (ok1) z1 = (g_off[mask0 + r1 + 1] - g_off[mask0 + r1]) == 0;
        }
        #pragma unroll
        for (int t = 0; t < 16; t++) {
            float2 bv = *(const float2*)&bias[t * 8 + cq];
            if (ok0) {
                float2 v;
                if (z0) v = make_float2(0.f, 0.f);
                else    v = make_float2(acc[o][t][0] + bv.x, acc[o][t][1] + bv.y);
                *(float2*)&C[(size_t)r0 * 128 + t * 8 + cq] = v;
            }
            if (ok1) {
                float2 v;
                if (z1) v = make_float2(0.f, 0.f);
                else    v = make_float2(acc[o][t][2] + bv.x, acc[o][t][3] + bv.y);
                *(float2*)&C[(size_t)r1 * 128 + t * 8 + cq] = v;
            }
        }
    }
}

#define N_CD 391
#define N_W  235
// Dual c+cd GEMM over x_paper (391 blocks).
__global__ void __launch_bounds__(256, 1)
cdgemm(const float* __restrict__ xp,
       const float* __restrict__ bc, const float* __restrict__ bcd) {
    extern __shared__ char smraw[];
    gemm_tile<2>(s2u(smraw), xp, NP, blockIdx.x * 128,
                 2, bc,  g_Wh + NA * D, -1,
                 3, bcd, g_Wh + (NA + NP) * D);
}
// w (235 blocks) + h (1 block) in one launch.
__global__ void __launch_bounds__(256, 1)
whgemm(const float* __restrict__ xa, const float* __restrict__ xs,
       const float* __restrict__ bw, const float* __restrict__ bh) {
    extern __shared__ char smraw[];
    uint32_t sb = s2u(smraw);
    int b = blockIdx.x;
    if (b < N_W)
        gemm_tile<1>(sb, xa, NA, b * 128, 1, bw, g_Wh, -1, 0, nullptr, nullptr);
    else
        gemm_tile<1>(sb, xs, NS, 0, 5, bh, g_Wh + (NA + 2 * NP) * D, -1,
                     0, nullptr, nullptr);
}
// Epilogue GEMMs: wb (235 blocks) + ia (1 block).
__global__ void __launch_bounds__(256, 1)
epigemm(const float* __restrict__ bwb, const float* __restrict__ bia,
        float* __restrict__ outA, float* __restrict__ outS) {
    extern __shared__ char smraw[];
    uint32_t sb = s2u(smraw);
    int b = blockIdx.x;
    if (b < N_W)
        gemm_tile<1>(sb, g_agg, NA, b * 128, 0, bwb, outA, 0, 0, nullptr, nullptr);
    else
        gemm_tile<1>(sb, g_agg + NA * D, NS, 0, 4, bia, outS, 180004,
                     0, nullptr, nullptr);
}

// ===========================================================================
// Fused raw-feature aggregations: author (blocks<3750) + subject (30 blocks).
// ===========================================================================
__global__ void aggAS(const float* __restrict__ xp) {
    int b = blockIdx.x;
    if (b < 3750) {
        int w = b * 8 + (threadIdx.x >> 5);
        if (w >= NA) return;
        int lane = threadIdx.x & 31;
        int s = g_off[w];
        int e = g_off[w + 1];
        int cnt = e - s;
        float4 sum = make_float4(0.f, 0.f, 0.f, 0.f);
        int idx = s;
        for (; idx + 3 < e; idx += 4) {
            int a0 = g_srt[idx];
            int a1 = g_srt[idx + 1];
            int a2 = g_srt[idx + 2];
            int a3 = g_srt[idx + 3];
            float4 v0 = *(const float4*)&xp[a0 * D + lane * 4];
            float4 v1 = *(const float4*)&xp[a1 * D + lane * 4];
            float4 v2 = *(const float4*)&xp[a2 * D + lane * 4];
            float4 v3 = *(const float4*)&xp[a3 * D + lane * 4];
            sum.x += (v0.x + v1.x) + (v2.x + v3.x);
            sum.y += (v0.y + v1.y) + (v2.y + v3.y);
            sum.z += (v0.z + v1.z) + (v2.z + v3.z);
            sum.w += (v0.w + v1.w) + (v2.w + v3.w);
        }
        for (; idx < e; idx++) {
            int a0 = g_srt[idx];
            float4 v0 = *(const float4*)&xp[a0 * D + lane * 4];
            sum.x += v0.x; sum.y += v0.y; sum.z += v0.z; sum.w += v0.w;
        }
        float inv = (cnt > 0) ? 1.f / (float)cnt : 0.f;
        *(float4*)&g_agg[w * D + lane * 4] =
            make_float4(sum.x * inv, sum.y * inv, sum.z * inv, sum.w * inv);
    } else {
        int dno = (b - 3750) * 2 + (threadIdx.x >> 7);
        int j = threadIdx.x & 127;
        if (dno >= NS) return;
        int s = g_off[180004 + dno];
        int e = g_off[180004 + dno + 1];
        int cnt = e - s;
        float sum = 0.f;
        int idx = s;
        for (; idx + 3 < e; idx += 4) {
            int a = g_srt[1400000 + idx];
            int bb = g_srt[1400000 + idx + 1];
            int c = g_srt[1400000 + idx + 2];
            int d = g_srt[1400000 + idx + 3];
            sum += xp[a * D + j] + xp[bb * D + j] + xp[c * D + j] + xp[d * D + j];
        }
        for (; idx < e; idx++) sum += xp[g_srt[1400000 + idx] * D + j];
        g_agg[(NA + dno) * D + j] = (cnt > 0) ? sum / (float)cnt : 0.f;
    }
}

// ===========================================================================
// Paper gather over a PAIR of relations; warp per dst; MLP=4.
// ===========================================================================
__global__ void agg_pair(float* __restrict__ out,
                         int offB0, int srtB0, int whB0,
                         int offB1, int srtB1, int whB1, int accum) {
    int w = (blockIdx.x * blockDim.x + threadIdx.x) >> 5;
    if (w >= NP) return;
    int lane = threadIdx.x & 31;
    float4 acc = accum ? *(float4*)&out[w * D + lane * 4]
                       : make_float4(0.f, 0.f, 0.f, 0.f);
    #pragma unroll
    for (int r = 0; r < 2; r++) {
        int offB = r ? offB1 : offB0;
        int srtB = r ? srtB1 : srtB0;
        const float* whb = g_Wh + (r ? whB1 : whB0);
        int s = g_off[offB + w];
        int e = g_off[offB + w + 1];
        int cnt = e - s;
        if (cnt > 0) {
            float4 sum = make_float4(0.f, 0.f, 0.f, 0.f);
            int idx = s;
            for (; idx + 3 < e; idx += 4) {
                int a0 = g_srt[srtB + idx];
                int a1 = g_srt[srtB + idx + 1];
                int a2 = g_srt[srtB + idx + 2];
                int a3 = g_srt[srtB + idx + 3];
                float4 v0 = *(const float4*)&whb[a0 * D + lane * 4];
                float4 v1 = *(const float4*)&whb[a1 * D + lane * 4];
                float4 v2 = *(const float4*)&whb[a2 * D + lane * 4];
                float4 v3 = *(const float4*)&whb[a3 * D + lane * 4];
                sum.x += (v0.x + v1.x) + (v2.x + v3.x);
                sum.y += (v0.y + v1.y) + (v2.y + v3.y);
                sum.z += (v0.z + v1.z) + (v2.z + v3.z);
                sum.w += (v0.w + v1.w) + (v2.w + v3.w);
            }
            for (; idx < e; idx++) {
                int a0 = g_srt[srtB + idx];
                float4 v0 = *(const float4*)&whb[a0 * D + lane * 4];
                sum.x += v0.x; sum.y += v0.y; sum.z += v0.z; sum.w += v0.w;
            }
            float inv = 1.f / (float)cnt;
            acc.x += sum.x * inv; acc.y += sum.y * inv;
            acc.z += sum.z * inv; acc.w += sum.w * inv;
        }
    }
    *(float4*)&out[w * D + lane * 4] = acc;
}

// ===========================================================================
extern "C" void kernel_launch(void* const* d_in, const int* in_sizes, int n_in,
                              void* d_out, int out_size) {
    const float* x_paper   = (const float*)d_in[0];
    const float* x_author  = (const float*)d_in[1];
    const float* x_subject = (const float*)d_in[2];
    const float* W_wb = (const float*)d_in[3];  const float* b_wb = (const float*)d_in[4];
    const float* W_w  = (const float*)d_in[5];  const float* b_w  = (const float*)d_in[6];
    const float* W_c  = (const float*)d_in[7];  const float* b_c  = (const float*)d_in[8];
    const float* W_cd = (const float*)d_in[9];  const float* b_cd = (const float*)d_in[10];
    const float* W_ia = (const float*)d_in[11]; const float* b_ia = (const float*)d_in[12];
    const float* W_h  = (const float*)d_in[13]; const float* b_h  = (const float*)d_in[14];
    const int* src_wb = (const int*)d_in[15];   const int* dst_wb = (const int*)d_in[16];
    const int* src_w  = (const int*)d_in[17];   const int* dst_w  = (const int*)d_in[18];
    const int* src_c  = (const int*)d_in[19];   const int* dst_c  = (const int*)d_in[20];
    const int* src_cd = (const int*)d_in[21];   const int* dst_cd = (const int*)d_in[22];
    const int* src_ia = (const int*)d_in[23];   const int* dst_ia = (const int*)d_in[24];
    const int* src_h  = (const int*)d_in[25];   const int* dst_h  = (const int*)d_in[26];

    float* out         = (float*)d_out;
    float* out_paper   = out;
    float* out_author  = out + NP * D;
    float* out_subject = out + (NP + NA) * D;

    static cudaStream_t s1 = nullptr, s2 = nullptr;
    static cudaEvent_t evW, evCD, evB, evF, evD;
    if (s1 == nullptr) {
        cudaStreamCreateWithFlags(&s1, cudaStreamNonBlocking);
        cudaStreamCreateWithFlags(&s2, cudaStreamNonBlocking);
        cudaEventCreateWithFlags(&evW,  cudaEventDisableTiming);
        cudaEventCreateWithFlags(&evCD, cudaEventDisableTiming);
        cudaEventCreateWithFlags(&evB,  cudaEventDisableTiming);
        cudaEventCreateWithFlags(&evF,  cudaEventDisableTiming);
        cudaEventCreateWithFlags(&evD,  cudaEventDisableTiming);
        cudaFuncSetAttribute(cdgemm, cudaFuncAttributeMaxDynamicSharedMemorySize,
                             MMA_SMEM_DUAL);
        cudaFuncSetAttribute(whgemm, cudaFuncAttributeMaxDynamicSharedMemorySize,
                             MMA_SMEM_SINGLE);
        cudaFuncSetAttribute(epigemm, cudaFuncAttributeMaxDynamicSharedMemorySize,
                             MMA_SMEM_SINGLE);
    }

    // s0: prep (weights + deg zero + chain init) — root of both chains.
    prep<<<6 + (NDST_PAD + 255) / 256, 256>>>(W_wb, W_w, W_c, W_cd, W_ia, W_h);
    cudaEventRecord(evW, 0);

    // s1: GEMMs (c+cd first for the early gather).
    cudaStreamWaitEvent(s1, evW, 0);
    cdgemm<<<N_CD, 256, MMA_SMEM_DUAL, s1>>>(x_paper, b_c, b_cd);
    cudaEventRecord(evCD, s1);
    whgemm<<<N_W + 1, 256, MMA_SMEM_SINGLE, s1>>>(x_author, x_subject, b_w, b_h);
    cudaEventRecord(evB, s1);

    // s0: CSR build.
    count_kernel<<<(375000 + 255) / 256, 256>>>(dst_wb, dst_w, dst_c, dst_cd,
                                                dst_ia, dst_h);
    scan_main<<<NCHUNK, 1024>>>();
    remap_kernel<<<(NOFF_TOT + 255) / 256, 256>>>();
    fill_kernel<<<(375000 + 255) / 256, 256>>>(src_wb, dst_wb, src_w, dst_w,
                                               src_c, dst_c, src_cd, dst_cd,
                                               src_ia, dst_ia, src_h, dst_h);
    cudaEventRecord(evF, 0);

    // s2: raw-feature aggregations then epilogue GEMMs.
    cudaStreamWaitEvent(s2, evF, 0);
    aggAS<<<3780, 256, 0, s2>>>(x_paper);
    epigemm<<<N_W + 1, 256, MMA_SMEM_SINGLE, s2>>>(
        b_wb, b_ia, out_author, out_subject);
    cudaEventRecord(evD, s2);

    // s0: paper gathers (CSR done in-stream; Wh via events).
    cudaStreamWaitEvent(0, evCD, 0);
    agg_pair<<<(NP * 32 + 255) / 256, 256>>>(
        out_paper, 80002, 400000, NA * D,
                   130003, 900000, (NA + NP) * D, 0);
    cudaStreamWaitEvent(0, evB, 0);
    agg_pair<<<(NP * 32 + 255) / 256, 256>>>(
        out_paper, 30001, 200000, 0,
                   180065, 1450000, (NA + 2 * NP) * D, 1);

    // join
    cudaStreamWaitEvent(0, evD, 0);
}